// round 1
// baseline (speedup 1.0000x reference)
#include <cuda_runtime.h>
#include <math.h>

#define T_DIM 8192
#define D_DIM 512

// Scratch (allocation-free rule: __device__ globals)
__device__ float g_hnorm[T_DIM * D_DIM];
__device__ float g_q[T_DIM * D_DIM];
__device__ float g_k[T_DIM * D_DIM];
__device__ float g_v[T_DIM * D_DIM];
__device__ float g_av[T_DIM * D_DIM];
__device__ float g_S[(size_t)T_DIM * T_DIM];   // 256 MB score matrix

// ---------------------------------------------------------------------------
// LayerNorm: one block (128 threads) per row of 512 floats (float4 per thread)
// ---------------------------------------------------------------------------
__global__ void ln_kernel(const float* __restrict__ h,
                          const float* __restrict__ w,
                          const float* __restrict__ b,
                          float* __restrict__ out)
{
    int row = blockIdx.x;
    int t = threadIdx.x;                  // 0..127
    const float4* hr = (const float4*)(h + (size_t)row * D_DIM);
    float4 x = hr[t];
    float s  = x.x + x.y + x.z + x.w;
    float ss = x.x * x.x + x.y * x.y + x.z * x.z + x.w * x.w;

    // warp reduce
    #pragma unroll
    for (int o = 16; o; o >>= 1) {
        s  += __shfl_xor_sync(0xffffffffu, s,  o);
        ss += __shfl_xor_sync(0xffffffffu, ss, o);
    }
    __shared__ float red[2][4];
    int lane = t & 31, warp = t >> 5;
    if (lane == 0) { red[0][warp] = s; red[1][warp] = ss; }
    __syncthreads();
    float a = red[0][0] + red[0][1] + red[0][2] + red[0][3];
    float c = red[1][0] + red[1][1] + red[1][2] + red[1][3];
    float mean = a * (1.0f / D_DIM);
    float var  = c * (1.0f / D_DIM) - mean * mean;
    float rstd = rsqrtf(var + 1e-5f);

    float4 wv = ((const float4*)w)[t];
    float4 bv = ((const float4*)b)[t];
    float4 o;
    o.x = (x.x - mean) * rstd * wv.x + bv.x;
    o.y = (x.y - mean) * rstd * wv.y + bv.y;
    o.z = (x.z - mean) * rstd * wv.z + bv.z;
    o.w = (x.w - mean) * rstd * wv.w + bv.w;
    ((float4*)(out + (size_t)row * D_DIM))[t] = o;
}

// ---------------------------------------------------------------------------
// GEMM NT:  C[M,N] = scale * (A[M,K] @ B[N,K]^T) (+ residual)
// Tiles: BM=128, BN=64, BK=16, 256 threads, 8x4 microtile per thread.
// CAUSAL=1: skip blocks fully above the diagonal (used for Q@K^T).
// ---------------------------------------------------------------------------
template<int CAUSAL>
__global__ void gemm_nt(const float* __restrict__ A,
                        const float* __restrict__ B,
                        float* __restrict__ C,
                        const float* __restrict__ res,
                        int M, int N, int K, float scale)
{
    const int BM = 128, BN = 64, BK = 16;
    int m0 = blockIdx.y * BM;
    int n0 = blockIdx.x * BN;
    if (CAUSAL && n0 > m0 + BM - 1) return;

    __shared__ float As[BK][BM];
    __shared__ float Bs[BK][BN];

    int t  = threadIdx.x;          // 0..255
    int tx = t & 15;               // col group (4 cols)
    int ty = t >> 4;               // row group (8 rows)

    float acc[8][4];
    #pragma unroll
    for (int i = 0; i < 8; i++)
        #pragma unroll
        for (int j = 0; j < 4; j++) acc[i][j] = 0.0f;

    for (int k0 = 0; k0 < K; k0 += BK) {
        // load A tile (128x16 = 512 float4), transposed into As[k][m]
        #pragma unroll
        for (int i = 0; i < 2; i++) {
            int f   = t + i * 256;
            int row = f >> 2;
            int kc  = (f & 3) << 2;
            float4 av = *(const float4*)(A + (size_t)(m0 + row) * K + k0 + kc);
            As[kc + 0][row] = av.x;
            As[kc + 1][row] = av.y;
            As[kc + 2][row] = av.z;
            As[kc + 3][row] = av.w;
        }
        // load B tile (64x16 = 256 float4), transposed into Bs[k][n]
        {
            int row = t >> 2;
            int kc  = (t & 3) << 2;
            float4 bv = *(const float4*)(B + (size_t)(n0 + row) * K + k0 + kc);
            Bs[kc + 0][row] = bv.x;
            Bs[kc + 1][row] = bv.y;
            Bs[kc + 2][row] = bv.z;
            Bs[kc + 3][row] = bv.w;
        }
        __syncthreads();

        #pragma unroll
        for (int kk = 0; kk < BK; kk++) {
            float af[8], bf[4];
            *(float4*)&af[0] = *(const float4*)&As[kk][ty * 8];
            *(float4*)&af[4] = *(const float4*)&As[kk][ty * 8 + 4];
            *(float4*)&bf[0] = *(const float4*)&Bs[kk][tx * 4];
            #pragma unroll
            for (int i = 0; i < 8; i++)
                #pragma unroll
                for (int j = 0; j < 4; j++)
                    acc[i][j] += af[i] * bf[j];
        }
        __syncthreads();
    }

    #pragma unroll
    for (int i = 0; i < 8; i++) {
        int m = m0 + ty * 8 + i;
        size_t base = (size_t)m * N + n0 + tx * 4;
        float4 o;
        o.x = acc[i][0] * scale;
        o.y = acc[i][1] * scale;
        o.z = acc[i][2] * scale;
        o.w = acc[i][3] * scale;
        if (res) {
            float4 r = *(const float4*)(res + base);
            o.x += r.x; o.y += r.y; o.z += r.z; o.w += r.w;
        }
        *(float4*)(C + base) = o;
    }
}

// ---------------------------------------------------------------------------
// Causal row softmax over S (in place). One block (256 thr) per row.
// Normalized probs for j<=row; zeros written out to the next multiple of 128
// so the PV gemm can cap its k-loop at m0+128 per row-block.
// ---------------------------------------------------------------------------
__device__ __forceinline__ float block_reduce(float v, bool is_max)
{
    __shared__ float sm[8];
    __syncthreads();           // protect shared reuse across calls
    #pragma unroll
    for (int o = 16; o; o >>= 1) {
        float u = __shfl_xor_sync(0xffffffffu, v, o);
        v = is_max ? fmaxf(v, u) : (v + u);
    }
    int lane = threadIdx.x & 31, warp = threadIdx.x >> 5;
    if (lane == 0) sm[warp] = v;
    __syncthreads();
    float r = sm[0];
    #pragma unroll
    for (int i = 1; i < 8; i++)
        r = is_max ? fmaxf(r, sm[i]) : (r + sm[i]);
    return r;
}

__global__ void softmax_causal(float* __restrict__ S)
{
    int row = blockIdx.x;
    int t = threadIdx.x;               // 0..255
    int n = row + 1;                   // valid length
    float* Srow = S + (size_t)row * T_DIM;

    float v[32];
    float mx = -INFINITY;
    #pragma unroll
    for (int it = 0; it < 32; it++) {
        int j = (it << 8) + t;
        float x = (j < n) ? Srow[j] : -INFINITY;
        v[it] = x;
        mx = fmaxf(mx, x);
    }
    mx = block_reduce(mx, true);

    float sum = 0.0f;
    #pragma unroll
    for (int it = 0; it < 32; it++) {
        int j = (it << 8) + t;
        float e = (j < n) ? expf(v[it] - mx) : 0.0f;
        v[it] = e;
        sum += e;
    }
    sum = block_reduce(sum, false);
    float inv = 1.0f / sum;

    int zend = (n + 127) & ~127;       // zero-pad region end
    #pragma unroll
    for (int it = 0; it < 32; it++) {
        int j = (it << 8) + t;
        if (j < zend) Srow[j] = v[it] * inv;
    }
}

// ---------------------------------------------------------------------------
// GEMM NN (causal-capped):  C[M,N] = A[M,K] @ B[K,N], k-loop capped at m0+BM.
// A = softmaxed S (lda = K = 8192), B = V [8192,512].
// ---------------------------------------------------------------------------
__global__ void gemm_nn_causal(const float* __restrict__ A,
                               const float* __restrict__ B,
                               float* __restrict__ C,
                               int M, int N, int K)
{
    const int BM = 128, BN = 64, BK = 16;
    int m0 = blockIdx.y * BM;
    int n0 = blockIdx.x * BN;
    int kend = min(K, m0 + BM);

    __shared__ float As[BK][BM];
    __shared__ float Bs[BK][BN];

    int t  = threadIdx.x;
    int tx = t & 15;
    int ty = t >> 4;

    float acc[8][4];
    #pragma unroll
    for (int i = 0; i < 8; i++)
        #pragma unroll
        for (int j = 0; j < 4; j++) acc[i][j] = 0.0f;

    for (int k0 = 0; k0 < kend; k0 += BK) {
        // A tile (rows of S, k contiguous), transposed into As[k][m]
        #pragma unroll
        for (int i = 0; i < 2; i++) {
            int f   = t + i * 256;
            int row = f >> 2;
            int kc  = (f & 3) << 2;
            float4 av = *(const float4*)(A + (size_t)(m0 + row) * K + k0 + kc);
            As[kc + 0][row] = av.x;
            As[kc + 1][row] = av.y;
            As[kc + 2][row] = av.z;
            As[kc + 3][row] = av.w;
        }
        // B tile: 16 rows x 64 cols (n contiguous), direct layout
        {
            int kr = t >> 4;           // 0..15
            int c4 = t & 15;           // 0..15 (float4 cols)
            float4 bv = *(const float4*)(B + (size_t)(k0 + kr) * N + n0 + c4 * 4);
            *(float4*)&Bs[kr][c4 * 4] = bv;
        }
        __syncthreads();

        #pragma unroll
        for (int kk = 0; kk < BK; kk++) {
            float af[8], bf[4];
            *(float4*)&af[0] = *(const float4*)&As[kk][ty * 8];
            *(float4*)&af[4] = *(const float4*)&As[kk][ty * 8 + 4];
            *(float4*)&bf[0] = *(const float4*)&Bs[kk][tx * 4];
            #pragma unroll
            for (int i = 0; i < 8; i++)
                #pragma unroll
                for (int j = 0; j < 4; j++)
                    acc[i][j] += af[i] * bf[j];
        }
        __syncthreads();
    }

    #pragma unroll
    for (int i = 0; i < 8; i++) {
        int m = m0 + ty * 8 + i;
        size_t base = (size_t)m * N + n0 + tx * 4;
        float4 o;
        o.x = acc[i][0]; o.y = acc[i][1]; o.z = acc[i][2]; o.w = acc[i][3];
        *(float4*)(C + base) = o;
    }
}

// ---------------------------------------------------------------------------
extern "C" void kernel_launch(void* const* d_in, const int* in_sizes, int n_in,
                              void* d_out, int out_size)
{
    const float* h    = (const float*)d_in[0];
    const float* ln_w = (const float*)d_in[1];
    const float* ln_b = (const float*)d_in[2];
    const float* w_q  = (const float*)d_in[3];
    const float* w_k  = (const float*)d_in[4];
    const float* w_v  = (const float*)d_in[5];
    const float* w_o  = (const float*)d_in[6];
    float* out = (float*)d_out;

    float *hn, *q, *k, *v, *av, *S;
    cudaGetSymbolAddress((void**)&hn, g_hnorm);
    cudaGetSymbolAddress((void**)&q,  g_q);
    cudaGetSymbolAddress((void**)&k,  g_k);
    cudaGetSymbolAddress((void**)&v,  g_v);
    cudaGetSymbolAddress((void**)&av, g_av);
    cudaGetSymbolAddress((void**)&S,  g_S);

    const float inv_sqrt_d = 0.044194173824159216f;  // 1/sqrt(512)

    // 1) LayerNorm
    ln_kernel<<<T_DIM, 128>>>(h, ln_w, ln_b, hn);

    // 2) Q, K, V projections: x @ W^T  (NT gemm)
    dim3 gProj(D_DIM / 64, T_DIM / 128);  // (8, 64)
    gemm_nt<0><<<gProj, 256>>>(hn, w_q, q, nullptr, T_DIM, D_DIM, D_DIM, 1.0f);
    gemm_nt<0><<<gProj, 256>>>(hn, w_k, k, nullptr, T_DIM, D_DIM, D_DIM, 1.0f);
    gemm_nt<0><<<gProj, 256>>>(hn, w_v, v, nullptr, T_DIM, D_DIM, D_DIM, 1.0f);

    // 3) Scores = Q @ K^T * 1/sqrt(d), lower-triangular blocks only
    dim3 gScore(T_DIM / 64, T_DIM / 128); // (128, 64)
    gemm_nt<1><<<gScore, 256>>>(q, k, S, nullptr, T_DIM, T_DIM, D_DIM, inv_sqrt_d);

    // 4) Causal softmax (in place, zero-pads to 128-row boundary)
    softmax_causal<<<T_DIM, 256>>>(S);

    // 5) AV = softmax(S) @ V  (k-loop capped per row-block)
    dim3 gPV(D_DIM / 64, T_DIM / 128);    // (8, 64)
    gemm_nn_causal<<<gPV, 256>>>(S, v, av, T_DIM, D_DIM, T_DIM);

    // 6) out = h + AV @ W_o^T  (NT gemm with residual epilogue)
    gemm_nt<0><<<gProj, 256>>>(av, w_o, out, h, T_DIM, D_DIM, D_DIM, 1.0f);
}

// round 2
// speedup vs baseline: 2.0496x; 2.0496x over previous
#include <cuda_runtime.h>
#include <math.h>
#include <stdint.h>

#define T_DIM 8192
#define D_DIM 512

// Scratch (allocation-free rule: __device__ globals)
__device__ float g_hnorm[T_DIM * D_DIM];
__device__ float g_q[T_DIM * D_DIM];
__device__ float g_k[T_DIM * D_DIM];
__device__ float g_v[T_DIM * D_DIM];
__device__ float g_av[T_DIM * D_DIM];
__device__ float g_S[(size_t)T_DIM * T_DIM];   // 256 MB score matrix

// ---------------------------------------------------------------------------
// LayerNorm: one block (128 threads) per row of 512 floats
// ---------------------------------------------------------------------------
__global__ void ln_kernel(const float* __restrict__ h,
                          const float* __restrict__ w,
                          const float* __restrict__ b,
                          float* __restrict__ out)
{
    int row = blockIdx.x;
    int t = threadIdx.x;                  // 0..127
    const float4* hr = (const float4*)(h + (size_t)row * D_DIM);
    float4 x = hr[t];
    float s  = x.x + x.y + x.z + x.w;
    float ss = x.x * x.x + x.y * x.y + x.z * x.z + x.w * x.w;

    #pragma unroll
    for (int o = 16; o; o >>= 1) {
        s  += __shfl_xor_sync(0xffffffffu, s,  o);
        ss += __shfl_xor_sync(0xffffffffu, ss, o);
    }
    __shared__ float red[2][4];
    int lane = t & 31, warp = t >> 5;
    if (lane == 0) { red[0][warp] = s; red[1][warp] = ss; }
    __syncthreads();
    float a = red[0][0] + red[0][1] + red[0][2] + red[0][3];
    float c = red[1][0] + red[1][1] + red[1][2] + red[1][3];
    float mean = a * (1.0f / D_DIM);
    float var  = c * (1.0f / D_DIM) - mean * mean;
    float rstd = rsqrtf(var + 1e-5f);

    float4 wv = ((const float4*)w)[t];
    float4 bv = ((const float4*)b)[t];
    float4 o;
    o.x = (x.x - mean) * rstd * wv.x + bv.x;
    o.y = (x.y - mean) * rstd * wv.y + bv.y;
    o.z = (x.z - mean) * rstd * wv.z + bv.z;
    o.w = (x.w - mean) * rstd * wv.w + bv.w;
    ((float4*)(out + (size_t)row * D_DIM))[t] = o;
}

// ---------------------------------------------------------------------------
// TF32 helpers
// ---------------------------------------------------------------------------
__device__ __forceinline__ uint32_t f2tf32(float f) {
    uint32_t r;
    asm("cvt.rna.tf32.f32 %0, %1;" : "=r"(r) : "f"(f));
    return r;
}

__device__ __forceinline__ void mma_tf32(float* c, const uint32_t* a, const uint32_t* b) {
    asm volatile(
        "mma.sync.aligned.m16n8k8.row.col.f32.tf32.tf32.f32 "
        "{%0,%1,%2,%3}, {%4,%5,%6,%7}, {%8,%9}, {%0,%1,%2,%3};"
        : "+f"(c[0]), "+f"(c[1]), "+f"(c[2]), "+f"(c[3])
        : "r"(a[0]), "r"(a[1]), "r"(a[2]), "r"(a[3]),
          "r"(b[0]), "r"(b[1]));
}

// ---------------------------------------------------------------------------
// Tensor-core GEMM (tf32 mma.sync), 128x128x16 block tile, 8 warps (2x4),
// warp tile 64x32, double-buffered smem.
//   TRANSB=1:  C = scale*(A[M,K] @ B[N,K]^T) (+res)   (NT; nn.Linear layout)
//   TRANSB=0:  C = A[M,K] @ B[K,N]                    (NN; PV)
//   CAUSAL=1:  skip blocks fully above diagonal (scores)
//   CAPK=1:    cap k-loop at m0+BM (PV over zero-padded causal probs)
// ---------------------------------------------------------------------------
template<int TRANSB, int CAUSAL, int CAPK>
__global__ void __launch_bounds__(256)
gemm_mma(const float* __restrict__ A,
         const float* __restrict__ B,
         float* __restrict__ C,
         const float* __restrict__ res,
         int M, int N, int K,
         int lda, int ldb, int ldc,
         float scale)
{
    const int BM = 128, BN = 128, BK = 16;
    const int LDS_S = BM + 4;                 // padded stride (132)

    int m0 = blockIdx.y * BM;
    int n0 = blockIdx.x * BN;
    if (CAUSAL && n0 > m0 + BM - 1) return;

    __shared__ float As[2][BK][LDS_S];
    __shared__ float Bs[2][BK][LDS_S];

    int t    = threadIdx.x;                   // 0..255
    int lane = t & 31;
    int warp = t >> 5;                        // 0..7
    int gid  = lane >> 2;                     // 0..7
    int tig  = lane & 3;                      // 0..3
    int wm   = (warp >> 2) * 64;              // warp M offset (0,64)
    int wn   = (warp & 3) * 32;               // warp N offset (0..96)

    int kend  = CAPK ? min(K, m0 + BM) : K;
    int niter = kend / BK;

    // gmem load indices
    int arow = t >> 2;                        // for f = t and t+256: rows t>>2, (t+256)>>2
    int akc  = (t & 3) << 2;

    float acc[4][4][4];
    #pragma unroll
    for (int mi = 0; mi < 4; mi++)
        #pragma unroll
        for (int ni = 0; ni < 4; ni++)
            #pragma unroll
            for (int r = 0; r < 4; r++) acc[mi][ni][r] = 0.0f;

    float4 areg[2], breg[2];

    // ---- prologue: load tile 0 ----
    {
        int k0 = 0;
        #pragma unroll
        for (int i = 0; i < 2; i++) {
            int f = t + i * 256;
            int row = f >> 2, kc = (f & 3) << 2;
            areg[i] = *(const float4*)(A + (size_t)(m0 + row) * lda + k0 + kc);
        }
        if (TRANSB) {
            #pragma unroll
            for (int i = 0; i < 2; i++) {
                int f = t + i * 256;
                int row = f >> 2, kc = (f & 3) << 2;
                breg[i] = *(const float4*)(B + (size_t)(n0 + row) * ldb + k0 + kc);
            }
        } else {
            #pragma unroll
            for (int i = 0; i < 2; i++) {
                int f = t + i * 256;
                int kr = f >> 5, c4 = f & 31;
                breg[i] = *(const float4*)(B + (size_t)(k0 + kr) * ldb + n0 + c4 * 4);
            }
        }
        #pragma unroll
        for (int i = 0; i < 2; i++) {
            int f = t + i * 256;
            int row = f >> 2, kc = (f & 3) << 2;
            As[0][kc + 0][row] = areg[i].x;
            As[0][kc + 1][row] = areg[i].y;
            As[0][kc + 2][row] = areg[i].z;
            As[0][kc + 3][row] = areg[i].w;
        }
        if (TRANSB) {
            #pragma unroll
            for (int i = 0; i < 2; i++) {
                int f = t + i * 256;
                int row = f >> 2, kc = (f & 3) << 2;
                Bs[0][kc + 0][row] = breg[i].x;
                Bs[0][kc + 1][row] = breg[i].y;
                Bs[0][kc + 2][row] = breg[i].z;
                Bs[0][kc + 3][row] = breg[i].w;
            }
        } else {
            #pragma unroll
            for (int i = 0; i < 2; i++) {
                int f = t + i * 256;
                int kr = f >> 5, c4 = f & 31;
                *(float4*)&Bs[0][kr][c4 * 4] = breg[i];
            }
        }
        __syncthreads();
    }

    // ---- main loop ----
    for (int it = 0; it < niter; it++) {
        int buf = it & 1;
        bool more = (it + 1 < niter);

        if (more) {
            int k0 = (it + 1) * BK;
            #pragma unroll
            for (int i = 0; i < 2; i++) {
                int f = t + i * 256;
                int row = f >> 2, kc = (f & 3) << 2;
                areg[i] = *(const float4*)(A + (size_t)(m0 + row) * lda + k0 + kc);
            }
            if (TRANSB) {
                #pragma unroll
                for (int i = 0; i < 2; i++) {
                    int f = t + i * 256;
                    int row = f >> 2, kc = (f & 3) << 2;
                    breg[i] = *(const float4*)(B + (size_t)(n0 + row) * ldb + k0 + kc);
                }
            } else {
                #pragma unroll
                for (int i = 0; i < 2; i++) {
                    int f = t + i * 256;
                    int kr = f >> 5, c4 = f & 31;
                    breg[i] = *(const float4*)(B + (size_t)(k0 + kr) * ldb + n0 + c4 * 4);
                }
            }
        }

        // compute on smem[buf]
        #pragma unroll
        for (int ks = 0; ks < 2; ks++) {
            int kb = ks * 8;
            uint32_t afr[4][4];
            #pragma unroll
            for (int mi = 0; mi < 4; mi++) {
                int m = wm + mi * 16 + gid;
                afr[mi][0] = f2tf32(As[buf][kb + tig][m]);
                afr[mi][1] = f2tf32(As[buf][kb + tig][m + 8]);
                afr[mi][2] = f2tf32(As[buf][kb + tig + 4][m]);
                afr[mi][3] = f2tf32(As[buf][kb + tig + 4][m + 8]);
            }
            uint32_t bfr[4][2];
            #pragma unroll
            for (int ni = 0; ni < 4; ni++) {
                int n = wn + ni * 8 + gid;
                bfr[ni][0] = f2tf32(Bs[buf][kb + tig][n]);
                bfr[ni][1] = f2tf32(Bs[buf][kb + tig + 4][n]);
            }
            #pragma unroll
            for (int mi = 0; mi < 4; mi++)
                #pragma unroll
                for (int ni = 0; ni < 4; ni++)
                    mma_tf32(acc[mi][ni], afr[mi], bfr[ni]);
        }

        if (more) {
            int nb = buf ^ 1;
            #pragma unroll
            for (int i = 0; i < 2; i++) {
                int f = t + i * 256;
                int row = f >> 2, kc = (f & 3) << 2;
                As[nb][kc + 0][row] = areg[i].x;
                As[nb][kc + 1][row] = areg[i].y;
                As[nb][kc + 2][row] = areg[i].z;
                As[nb][kc + 3][row] = areg[i].w;
            }
            if (TRANSB) {
                #pragma unroll
                for (int i = 0; i < 2; i++) {
                    int f = t + i * 256;
                    int row = f >> 2, kc = (f & 3) << 2;
                    Bs[nb][kc + 0][row] = breg[i].x;
                    Bs[nb][kc + 1][row] = breg[i].y;
                    Bs[nb][kc + 2][row] = breg[i].z;
                    Bs[nb][kc + 3][row] = breg[i].w;
                }
            } else {
                #pragma unroll
                for (int i = 0; i < 2; i++) {
                    int f = t + i * 256;
                    int kr = f >> 5, c4 = f & 31;
                    *(float4*)&Bs[nb][kr][c4 * 4] = breg[i];
                }
            }
            __syncthreads();
        }
    }

    // ---- epilogue ----
    #pragma unroll
    for (int mi = 0; mi < 4; mi++) {
        #pragma unroll
        for (int ni = 0; ni < 4; ni++) {
            int row = m0 + wm + mi * 16 + gid;
            int col = n0 + wn + ni * 8 + tig * 2;
            float2 o0, o1;
            o0.x = acc[mi][ni][0] * scale;
            o0.y = acc[mi][ni][1] * scale;
            o1.x = acc[mi][ni][2] * scale;
            o1.y = acc[mi][ni][3] * scale;
            size_t i0 = (size_t)row * ldc + col;
            size_t i1 = (size_t)(row + 8) * ldc + col;
            if (res) {
                float2 r0 = *(const float2*)(res + i0);
                float2 r1 = *(const float2*)(res + i1);
                o0.x += r0.x; o0.y += r0.y;
                o1.x += r1.x; o1.y += r1.y;
            }
            *(float2*)(C + i0) = o0;
            *(float2*)(C + i1) = o1;
        }
    }
}

// ---------------------------------------------------------------------------
// Causal row softmax over S (in place). One block (256 thr) per row.
// Zero-pads to next 128-column boundary so PV can cap its k-loop.
// ---------------------------------------------------------------------------
__device__ __forceinline__ float block_reduce(float v, bool is_max)
{
    __shared__ float sm[8];
    __syncthreads();
    #pragma unroll
    for (int o = 16; o; o >>= 1) {
        float u = __shfl_xor_sync(0xffffffffu, v, o);
        v = is_max ? fmaxf(v, u) : (v + u);
    }
    int lane = threadIdx.x & 31, warp = threadIdx.x >> 5;
    if (lane == 0) sm[warp] = v;
    __syncthreads();
    float r = sm[0];
    #pragma unroll
    for (int i = 1; i < 8; i++)
        r = is_max ? fmaxf(r, sm[i]) : (r + sm[i]);
    return r;
}

__global__ void softmax_causal(float* __restrict__ S)
{
    int row = blockIdx.x;
    int t = threadIdx.x;               // 0..255
    int n = row + 1;                   // valid length
    float* Srow = S + (size_t)row * T_DIM;

    float v[32];
    float mx = -INFINITY;
    #pragma unroll
    for (int it = 0; it < 32; it++) {
        int j = (it << 8) + t;
        float x = (j < n) ? Srow[j] : -INFINITY;
        v[it] = x;
        mx = fmaxf(mx, x);
    }
    mx = block_reduce(mx, true);

    float sum = 0.0f;
    #pragma unroll
    for (int it = 0; it < 32; it++) {
        int j = (it << 8) + t;
        float e = (j < n) ? expf(v[it] - mx) : 0.0f;
        v[it] = e;
        sum += e;
    }
    sum = block_reduce(sum, false);
    float inv = 1.0f / sum;

    int zend = (n + 127) & ~127;
    #pragma unroll
    for (int it = 0; it < 32; it++) {
        int j = (it << 8) + t;
        if (j < zend) Srow[j] = v[it] * inv;
    }
}

// ---------------------------------------------------------------------------
extern "C" void kernel_launch(void* const* d_in, const int* in_sizes, int n_in,
                              void* d_out, int out_size)
{
    const float* h    = (const float*)d_in[0];
    const float* ln_w = (const float*)d_in[1];
    const float* ln_b = (const float*)d_in[2];
    const float* w_q  = (const float*)d_in[3];
    const float* w_k  = (const float*)d_in[4];
    const float* w_v  = (const float*)d_in[5];
    const float* w_o  = (const float*)d_in[6];
    float* out = (float*)d_out;

    float *hn, *q, *k, *v, *av, *S;
    cudaGetSymbolAddress((void**)&hn, g_hnorm);
    cudaGetSymbolAddress((void**)&q,  g_q);
    cudaGetSymbolAddress((void**)&k,  g_k);
    cudaGetSymbolAddress((void**)&v,  g_v);
    cudaGetSymbolAddress((void**)&av, g_av);
    cudaGetSymbolAddress((void**)&S,  g_S);

    const float inv_sqrt_d = 0.044194173824159216f;  // 1/sqrt(512)

    // 1) LayerNorm
    ln_kernel<<<T_DIM, 128>>>(h, ln_w, ln_b, hn);

    // 2) Q, K, V projections (NT)
    dim3 gProj(D_DIM / 128, T_DIM / 128);  // (4, 64)
    gemm_mma<1,0,0><<<gProj, 256>>>(hn, w_q, q, nullptr,
                                    T_DIM, D_DIM, D_DIM, D_DIM, D_DIM, D_DIM, 1.0f);
    gemm_mma<1,0,0><<<gProj, 256>>>(hn, w_k, k, nullptr,
                                    T_DIM, D_DIM, D_DIM, D_DIM, D_DIM, D_DIM, 1.0f);
    gemm_mma<1,0,0><<<gProj, 256>>>(hn, w_v, v, nullptr,
                                    T_DIM, D_DIM, D_DIM, D_DIM, D_DIM, D_DIM, 1.0f);

    // 3) Scores = Q @ K^T * 1/sqrt(d), lower-tri blocks only (NT, causal)
    dim3 gScore(T_DIM / 128, T_DIM / 128);  // (64, 64)
    gemm_mma<1,1,0><<<gScore, 256>>>(q, k, S, nullptr,
                                     T_DIM, T_DIM, D_DIM, D_DIM, D_DIM, T_DIM, inv_sqrt_d);

    // 4) Causal softmax (in place, zero-pads to 128-col boundary)
    softmax_causal<<<T_DIM, 256>>>(S);

    // 5) AV = softmax(S) @ V (NN, k-capped)
    dim3 gPV(D_DIM / 128, T_DIM / 128);  // (4, 64)
    gemm_mma<0,0,1><<<gPV, 256>>>(S, v, av, nullptr,
                                  T_DIM, D_DIM, T_DIM, T_DIM, D_DIM, D_DIM, 1.0f);

    // 6) out = h + AV @ W_o^T (NT with residual)
    gemm_mma<1,0,0><<<gProj, 256>>>(av, w_o, out, h,
                                    T_DIM, D_DIM, D_DIM, D_DIM, D_DIM, D_DIM, 1.0f);
}

// round 4
// speedup vs baseline: 3.9614x; 1.9328x over previous
#include <cuda_runtime.h>
#include <math.h>
#include <stdint.h>

#define T_DIM 8192
#define D_DIM 512

// Scratch (allocation-free rule: __device__ globals)
__device__ float g_hnorm[T_DIM * D_DIM];
__device__ float g_q[T_DIM * D_DIM];
__device__ float g_k[T_DIM * D_DIM];
__device__ float g_vt[T_DIM * D_DIM];          // V transposed: [d][T]
__device__ float g_v[T_DIM * D_DIM];
__device__ float g_av[T_DIM * D_DIM];
__device__ float g_S[(size_t)T_DIM * T_DIM];   // 256 MB score matrix

// ===========================================================================
// Helpers
// ===========================================================================
__device__ __forceinline__ uint32_t smem_u32(const void* p) {
    uint32_t a;
    asm("{ .reg .u64 t; cvta.to.shared.u64 t, %1; cvt.u32.u64 %0, t; }" : "=r"(a) : "l"(p));
    return a;
}
#define SW128(o) ((o) ^ ((((uint32_t)(o)) >> 3) & 0x70))

#define CP_ASYNC16(dst, src) \
    asm volatile("cp.async.cg.shared.global [%0], [%1], 16;" :: "r"(dst), "l"(src) : "memory")
#define CP_COMMIT() asm volatile("cp.async.commit_group;" ::: "memory")
#define CP_WAIT1()  asm volatile("cp.async.wait_group 1;" ::: "memory")

__device__ __forceinline__ void ldsm_x4(uint32_t& r0, uint32_t& r1, uint32_t& r2, uint32_t& r3,
                                        uint32_t addr) {
    asm volatile("ldmatrix.sync.aligned.m8n8.x4.shared.b16 {%0,%1,%2,%3}, [%4];"
                 : "=r"(r0), "=r"(r1), "=r"(r2), "=r"(r3) : "r"(addr));
}

__device__ __forceinline__ void mma_tf32(float* c, const uint32_t* a, const uint32_t* b) {
    asm volatile(
        "mma.sync.aligned.m16n8k8.row.col.f32.tf32.tf32.f32 "
        "{%0,%1,%2,%3}, {%4,%5,%6,%7}, {%8,%9}, {%0,%1,%2,%3};"
        : "+f"(c[0]), "+f"(c[1]), "+f"(c[2]), "+f"(c[3])
        : "r"(a[0]), "r"(a[1]), "r"(a[2]), "r"(a[3]),
          "r"(b[0]), "r"(b[1]));
}

// ===========================================================================
// LayerNorm: one block (128 threads) per row of 512 floats
// ===========================================================================
__global__ void ln_kernel(const float* __restrict__ h,
                          const float* __restrict__ w,
                          const float* __restrict__ b,
                          float* __restrict__ out)
{
    int row = blockIdx.x;
    int t = threadIdx.x;
    const float4* hr = (const float4*)(h + (size_t)row * D_DIM);
    float4 x = hr[t];
    float s  = x.x + x.y + x.z + x.w;
    float ss = x.x * x.x + x.y * x.y + x.z * x.z + x.w * x.w;

    #pragma unroll
    for (int o = 16; o; o >>= 1) {
        s  += __shfl_xor_sync(0xffffffffu, s,  o);
        ss += __shfl_xor_sync(0xffffffffu, ss, o);
    }
    __shared__ float red[2][4];
    int lane = t & 31, warp = t >> 5;
    if (lane == 0) { red[0][warp] = s; red[1][warp] = ss; }
    __syncthreads();
    float a = red[0][0] + red[0][1] + red[0][2] + red[0][3];
    float c = red[1][0] + red[1][1] + red[1][2] + red[1][3];
    float mean = a * (1.0f / D_DIM);
    float var  = c * (1.0f / D_DIM) - mean * mean;
    float rstd = rsqrtf(var + 1e-5f);

    float4 wv = ((const float4*)w)[t];
    float4 bv = ((const float4*)b)[t];
    float4 o;
    o.x = (x.x - mean) * rstd * wv.x + bv.x;
    o.y = (x.y - mean) * rstd * wv.y + bv.y;
    o.z = (x.z - mean) * rstd * wv.z + bv.z;
    o.w = (x.w - mean) * rstd * wv.w + bv.w;
    ((float4*)(out + (size_t)row * D_DIM))[t] = o;
}

// ===========================================================================
// 32x32 tiled transpose: out[d][T] = in[T][d]
// ===========================================================================
__global__ void transpose_kernel(const float* __restrict__ in, float* __restrict__ out)
{
    __shared__ float tile[32][33];
    int x0 = blockIdx.x * 32;   // d
    int y0 = blockIdx.y * 32;   // T
    int tx = threadIdx.x & 31, ty = threadIdx.x >> 5;   // 32 x 8
    #pragma unroll
    for (int i = 0; i < 32; i += 8)
        tile[ty + i][tx] = in[(size_t)(y0 + ty + i) * D_DIM + x0 + tx];
    __syncthreads();
    #pragma unroll
    for (int i = 0; i < 32; i += 8)
        out[(size_t)(x0 + ty + i) * T_DIM + y0 + tx] = tile[tx][ty + i];
}

// ===========================================================================
// TF32 mma.sync GEMM (NT): C[M,N] = scale*(A[M,K] @ B[N,K]^T) (+res)
// 128x128x32 block tile, 8 warps (2x4), warp tile 64x32.
// cp.async double-buffered smem (SW128-swizzled 128B rows), ldmatrix frags,
// raw fp32 fed to tf32 MMA (hardware truncation).
//   CAUSAL=1: skip blocks fully above diagonal
//   CAPK=1:   cap k-loop at m0+128 (PV over zero-padded causal probs)
// ===========================================================================
#define BK 32
#define TILE_B (128 * BK * 4)    // 16 KB per tile buffer
#define SM_A 0
#define SM_B (2 * TILE_B)
#define SM_TOT (4 * TILE_B)      // 64 KB

template<int CAUSAL, int CAPK>
__global__ void __launch_bounds__(256)
gemm_nt_tc(const float* __restrict__ A,
           const float* __restrict__ B,
           float* __restrict__ C,
           const float* __restrict__ res,
           int M, int N, int K,
           int lda, int ldb, int ldc,
           float scale)
{
    extern __shared__ char smem[];
    int m0 = blockIdx.y * 128;
    int n0 = blockIdx.x * 128;
    if (CAUSAL && n0 > m0 + 127) return;

    uint32_t sbase = smem_u32(smem);
    int t    = threadIdx.x;
    int lane = t & 31;
    int warp = t >> 5;
    int gid  = lane >> 2;
    int tig  = lane & 3;
    int wm   = (warp >> 2) * 64;
    int wn   = (warp & 3) * 32;

    int kend  = CAPK ? min(K, m0 + 128) : K;
    int niter = kend / BK;

    // loader indices: 4 chunks of 16B per thread per tile
    // f = t + i*256: row = f>>3 (0..127), kg = f&7 (16B col)
    auto load_tiles = [&](int buf, int k0) {
        #pragma unroll
        for (int i = 0; i < 4; i++) {
            int f = t + i * 256;
            int row = f >> 3, kg = f & 7;
            uint32_t off = SW128((uint32_t)(row * 128 + kg * 16));
            CP_ASYNC16(sbase + SM_A + buf * TILE_B + off,
                       A + (size_t)(m0 + row) * lda + k0 + kg * 4);
        }
        #pragma unroll
        for (int i = 0; i < 4; i++) {
            int f = t + i * 256;
            int row = f >> 3, kg = f & 7;
            uint32_t off = SW128((uint32_t)(row * 128 + kg * 16));
            CP_ASYNC16(sbase + SM_B + buf * TILE_B + off,
                       B + (size_t)(n0 + row) * ldb + k0 + kg * 4);
        }
    };

    float acc[4][4][4];
    #pragma unroll
    for (int mi = 0; mi < 4; mi++)
        #pragma unroll
        for (int ni = 0; ni < 4; ni++)
            #pragma unroll
            for (int r = 0; r < 4; r++) acc[mi][ni][r] = 0.0f;

    // per-thread ldmatrix address components (one address per thread per x4)
    int q   = lane >> 3;          // tile index within x4 (0..3)
    int r8  = lane & 7;           // row within tile
    int aq1 = (q & 1) * 8;        // A: +8 rows for tiles 1,3
    int aq2 = q >> 1;             // A: kg +1 for tiles 2,3
    int bq1 = (q >> 1) * 8;       // B: second n-tile for tiles 2,3
    int bq2 = q & 1;              // B: kg +1 for tiles 1,3

    // prologue: stage buffers 0 and 1
    load_tiles(0, 0);
    CP_COMMIT();
    if (niter > 1) load_tiles(1, BK);
    CP_COMMIT();

    for (int it = 0; it < niter; it++) {
        int buf = it & 1;
        CP_WAIT1();
        __syncthreads();

        uint32_t sa = sbase + SM_A + buf * TILE_B;
        uint32_t sb = sbase + SM_B + buf * TILE_B;

        #pragma unroll
        for (int ks = 0; ks < BK / 8; ks++) {
            uint32_t afr[4][4];
            #pragma unroll
            for (int mi = 0; mi < 4; mi++) {
                int row = wm + mi * 16 + aq1 + r8;
                int kg  = 2 * ks + aq2;
                uint32_t addr = sa + (uint32_t)(row * 128) + (uint32_t)(((kg) ^ (r8)) * 16);
                ldsm_x4(afr[mi][0], afr[mi][1], afr[mi][2], afr[mi][3], addr);
            }
            uint32_t bfr[4][2];
            #pragma unroll
            for (int p = 0; p < 2; p++) {
                int row = wn + p * 16 + bq1 + r8;
                int kg  = 2 * ks + bq2;
                uint32_t addr = sb + (uint32_t)(row * 128) + (uint32_t)(((kg) ^ (r8)) * 16);
                uint32_t r0, r1, r2, r3;
                ldsm_x4(r0, r1, r2, r3, addr);
                bfr[2 * p][0] = r0; bfr[2 * p][1] = r1;
                bfr[2 * p + 1][0] = r2; bfr[2 * p + 1][1] = r3;
            }
            #pragma unroll
            for (int mi = 0; mi < 4; mi++)
                #pragma unroll
                for (int ni = 0; ni < 4; ni++)
                    mma_tf32(acc[mi][ni], afr[mi], bfr[ni]);
        }

        __syncthreads();
        if (it + 2 < niter) load_tiles(buf, (it + 2) * BK);
        CP_COMMIT();
    }

    // epilogue
    #pragma unroll
    for (int mi = 0; mi < 4; mi++) {
        #pragma unroll
        for (int ni = 0; ni < 4; ni++) {
            int row = m0 + wm + mi * 16 + gid;
            int col = n0 + wn + ni * 8 + tig * 2;
            float2 o0, o1;
            o0.x = acc[mi][ni][0] * scale;
            o0.y = acc[mi][ni][1] * scale;
            o1.x = acc[mi][ni][2] * scale;
            o1.y = acc[mi][ni][3] * scale;
            size_t i0 = (size_t)row * ldc + col;
            size_t i1 = (size_t)(row + 8) * ldc + col;
            if (res) {
                float2 r0 = *(const float2*)(res + i0);
                float2 r1 = *(const float2*)(res + i1);
                o0.x += r0.x; o0.y += r0.y;
                o1.x += r1.x; o1.y += r1.y;
            }
            *(float2*)(C + i0) = o0;
            *(float2*)(C + i1) = o1;
        }
    }
}

// ===========================================================================
// Causal row softmax over S (in place). One block (256 thr) per row.
// Zero-pads to next 128-column boundary so PV can cap its k-loop.
// ===========================================================================
__device__ __forceinline__ float block_reduce(float v, bool is_max)
{
    __shared__ float sm[8];
    __syncthreads();
    #pragma unroll
    for (int o = 16; o; o >>= 1) {
        float u = __shfl_xor_sync(0xffffffffu, v, o);
        v = is_max ? fmaxf(v, u) : (v + u);
    }
    int lane = threadIdx.x & 31, warp = threadIdx.x >> 5;
    if (lane == 0) sm[warp] = v;
    __syncthreads();
    float r = sm[0];
    #pragma unroll
    for (int i = 1; i < 8; i++)
        r = is_max ? fmaxf(r, sm[i]) : (r + sm[i]);
    return r;
}

__global__ void softmax_causal(float* __restrict__ S)
{
    int row = blockIdx.x;
    int t = threadIdx.x;
    int n = row + 1;
    float* Srow = S + (size_t)row * T_DIM;

    float v[32];
    float mx = -INFINITY;
    #pragma unroll
    for (int it = 0; it < 32; it++) {
        int j = (it << 8) + t;
        float x = (j < n) ? Srow[j] : -INFINITY;
        v[it] = x;
        mx = fmaxf(mx, x);
    }
    mx = block_reduce(mx, true);

    float sum = 0.0f;
    #pragma unroll
    for (int it = 0; it < 32; it++) {
        int j = (it << 8) + t;
        float e = (j < n) ? expf(v[it] - mx) : 0.0f;
        v[it] = e;
        sum += e;
    }
    sum = block_reduce(sum, false);
    float inv = 1.0f / sum;

    int zend = (n + 127) & ~127;
    #pragma unroll
    for (int it = 0; it < 32; it++) {
        int j = (it << 8) + t;
        if (j < zend) Srow[j] = v[it] * inv;
    }
}

// ===========================================================================
extern "C" void kernel_launch(void* const* d_in, const int* in_sizes, int n_in,
                              void* d_out, int out_size)
{
    const float* h    = (const float*)d_in[0];
    const float* ln_w = (const float*)d_in[1];
    const float* ln_b = (const float*)d_in[2];
    const float* w_q  = (const float*)d_in[3];
    const float* w_k  = (const float*)d_in[4];
    const float* w_v  = (const float*)d_in[5];
    const float* w_o  = (const float*)d_in[6];
    float* out = (float*)d_out;

    float *hn, *q, *k, *v, *vt, *av, *S;
    cudaGetSymbolAddress((void**)&hn, g_hnorm);
    cudaGetSymbolAddress((void**)&q,  g_q);
    cudaGetSymbolAddress((void**)&k,  g_k);
    cudaGetSymbolAddress((void**)&v,  g_v);
    cudaGetSymbolAddress((void**)&vt, g_vt);
    cudaGetSymbolAddress((void**)&av, g_av);
    cudaGetSymbolAddress((void**)&S,  g_S);

    cudaFuncSetAttribute((const void*)gemm_nt_tc<0,0>,
                         cudaFuncAttributeMaxDynamicSharedMemorySize, SM_TOT);
    cudaFuncSetAttribute((const void*)gemm_nt_tc<1,0>,
                         cudaFuncAttributeMaxDynamicSharedMemorySize, SM_TOT);
    cudaFuncSetAttribute((const void*)gemm_nt_tc<0,1>,
                         cudaFuncAttributeMaxDynamicSharedMemorySize, SM_TOT);

    const float inv_sqrt_d = 0.044194173824159216f;  // 1/sqrt(512)

    // 1) LayerNorm
    ln_kernel<<<T_DIM, 128>>>(h, ln_w, ln_b, hn);

    // 2) Q, K, V projections (NT)
    dim3 gProj(D_DIM / 128, T_DIM / 128);  // (4, 64)
    gemm_nt_tc<0,0><<<gProj, 256, SM_TOT>>>(hn, w_q, q, nullptr,
        T_DIM, D_DIM, D_DIM, D_DIM, D_DIM, D_DIM, 1.0f);
    gemm_nt_tc<0,0><<<gProj, 256, SM_TOT>>>(hn, w_k, k, nullptr,
        T_DIM, D_DIM, D_DIM, D_DIM, D_DIM, D_DIM, 1.0f);
    gemm_nt_tc<0,0><<<gProj, 256, SM_TOT>>>(hn, w_v, v, nullptr,
        T_DIM, D_DIM, D_DIM, D_DIM, D_DIM, D_DIM, 1.0f);

    // 2b) Transpose V -> Vt[d][T]
    dim3 gT(D_DIM / 32, T_DIM / 32);   // (16, 256)
    transpose_kernel<<<gT, 256>>>(v, vt);

    // 3) Scores = Q @ K^T * 1/sqrt(d), lower-tri blocks only (NT, causal)
    dim3 gScore(T_DIM / 128, T_DIM / 128);  // (64, 64)
    gemm_nt_tc<1,0><<<gScore, 256, SM_TOT>>>(q, k, S, nullptr,
        T_DIM, T_DIM, D_DIM, D_DIM, D_DIM, T_DIM, inv_sqrt_d);

    // 4) Causal softmax (in place, zero-pads to 128-col boundary)
    softmax_causal<<<T_DIM, 256>>>(S);

    // 5) AV = softmax(S) @ Vt^T (NT, k-capped)
    dim3 gPV(D_DIM / 128, T_DIM / 128);  // (4, 64)
    gemm_nt_tc<0,1><<<gPV, 256, SM_TOT>>>(S, vt, av, nullptr,
        T_DIM, D_DIM, T_DIM, T_DIM, T_DIM, D_DIM, 1.0f);

    // 6) out = h + AV @ W_o^T (NT with residual)
    gemm_nt_tc<0,0><<<gProj, 256, SM_TOT>>>(av, w_o, out, h,
        T_DIM, D_DIM, D_DIM, D_DIM, D_DIM, D_DIM, 1.0f);
}

// round 5
// speedup vs baseline: 4.0329x; 1.0181x over previous
#include <cuda_runtime.h>
#include <math.h>
#include <stdint.h>

#define T_DIM 8192
#define D_DIM 512

// Scratch (allocation-free rule: __device__ globals)
__device__ float g_hnorm[T_DIM * D_DIM];
__device__ float g_q[T_DIM * D_DIM];
__device__ float g_k[T_DIM * D_DIM];
__device__ float g_v[T_DIM * D_DIM];
__device__ float g_vt[T_DIM * D_DIM];          // V transposed: [d][T]
__device__ float g_av[T_DIM * D_DIM];
__device__ float g_wr[4][D_DIM * D_DIM];       // tf32-rounded weights
__device__ float g_S[(size_t)T_DIM * T_DIM];   // 256 MB score matrix

// ===========================================================================
// Helpers
// ===========================================================================
__device__ __forceinline__ uint32_t smem_u32(const void* p) {
    uint32_t a;
    asm("{ .reg .u64 t; cvta.to.shared.u64 t, %1; cvt.u32.u64 %0, t; }" : "=r"(a) : "l"(p));
    return a;
}
__device__ __forceinline__ float rnd_tf32(float f) {
    uint32_t r;
    asm("cvt.rna.tf32.f32 %0, %1;" : "=r"(r) : "f"(f));
    return __uint_as_float(r);
}
#define SW128(o) ((o) ^ ((((uint32_t)(o)) >> 3) & 0x70))

#define CP_ASYNC16(dst, src) \
    asm volatile("cp.async.cg.shared.global [%0], [%1], 16;" :: "r"(dst), "l"(src) : "memory")
#define CP_COMMIT() asm volatile("cp.async.commit_group;" ::: "memory")
#define CP_WAIT1()  asm volatile("cp.async.wait_group 1;" ::: "memory")

__device__ __forceinline__ void ldsm_x4(uint32_t& r0, uint32_t& r1, uint32_t& r2, uint32_t& r3,
                                        uint32_t addr) {
    asm volatile("ldmatrix.sync.aligned.m8n8.x4.shared.b16 {%0,%1,%2,%3}, [%4];"
                 : "=r"(r0), "=r"(r1), "=r"(r2), "=r"(r3) : "r"(addr));
}

__device__ __forceinline__ void mma_tf32(float* c, const uint32_t* a, const uint32_t* b) {
    asm volatile(
        "mma.sync.aligned.m16n8k8.row.col.f32.tf32.tf32.f32 "
        "{%0,%1,%2,%3}, {%4,%5,%6,%7}, {%8,%9}, {%0,%1,%2,%3};"
        : "+f"(c[0]), "+f"(c[1]), "+f"(c[2]), "+f"(c[3])
        : "r"(a[0]), "r"(a[1]), "r"(a[2]), "r"(a[3]),
          "r"(b[0]), "r"(b[1]));
}

// ===========================================================================
// Round a buffer to the tf32 grid (float4 per thread)
// ===========================================================================
__global__ void round_tf32_kernel(const float* __restrict__ in, float* __restrict__ out)
{
    int i = blockIdx.x * 256 + threadIdx.x;
    float4 v = ((const float4*)in)[i];
    float4 o;
    o.x = rnd_tf32(v.x); o.y = rnd_tf32(v.y); o.z = rnd_tf32(v.z); o.w = rnd_tf32(v.w);
    ((float4*)out)[i] = o;
}

// ===========================================================================
// LayerNorm: one block (128 threads) per row; output rounded to tf32 grid
// ===========================================================================
__global__ void ln_kernel(const float* __restrict__ h,
                          const float* __restrict__ w,
                          const float* __restrict__ b,
                          float* __restrict__ out)
{
    int row = blockIdx.x;
    int t = threadIdx.x;
    const float4* hr = (const float4*)(h + (size_t)row * D_DIM);
    float4 x = hr[t];
    float s  = x.x + x.y + x.z + x.w;
    float ss = x.x * x.x + x.y * x.y + x.z * x.z + x.w * x.w;

    #pragma unroll
    for (int o = 16; o; o >>= 1) {
        s  += __shfl_xor_sync(0xffffffffu, s,  o);
        ss += __shfl_xor_sync(0xffffffffu, ss, o);
    }
    __shared__ float red[2][4];
    int lane = t & 31, warp = t >> 5;
    if (lane == 0) { red[0][warp] = s; red[1][warp] = ss; }
    __syncthreads();
    float a = red[0][0] + red[0][1] + red[0][2] + red[0][3];
    float c = red[1][0] + red[1][1] + red[1][2] + red[1][3];
    float mean = a * (1.0f / D_DIM);
    float var  = c * (1.0f / D_DIM) - mean * mean;
    float rstd = rsqrtf(var + 1e-5f);

    float4 wv = ((const float4*)w)[t];
    float4 bv = ((const float4*)b)[t];
    float4 o;
    o.x = rnd_tf32((x.x - mean) * rstd * wv.x + bv.x);
    o.y = rnd_tf32((x.y - mean) * rstd * wv.y + bv.y);
    o.z = rnd_tf32((x.z - mean) * rstd * wv.z + bv.z);
    o.w = rnd_tf32((x.w - mean) * rstd * wv.w + bv.w);
    ((float4*)(out + (size_t)row * D_DIM))[t] = o;
}

// ===========================================================================
// 32x32 tiled transpose: out[d][T] = in[T][d]
// ===========================================================================
__global__ void transpose_kernel(const float* __restrict__ in, float* __restrict__ out)
{
    __shared__ float tile[32][33];
    int x0 = blockIdx.x * 32;   // d
    int y0 = blockIdx.y * 32;   // T
    int tx = threadIdx.x & 31, ty = threadIdx.x >> 5;   // 32 x 8
    #pragma unroll
    for (int i = 0; i < 32; i += 8)
        tile[ty + i][tx] = in[(size_t)(y0 + ty + i) * D_DIM + x0 + tx];
    __syncthreads();
    #pragma unroll
    for (int i = 0; i < 32; i += 8)
        out[(size_t)(x0 + ty + i) * T_DIM + y0 + tx] = tile[tx][ty + i];
}

// ===========================================================================
// TF32 mma.sync GEMM (NT): C[M,N] = scale*(A[M,K] @ B[N,K]^T) (+res)
// 128x128x32 block tile, 8 warps (2x4), warp tile 64x32.
// 3-stage cp.async ring (SW128-swizzled 128B rows), ldmatrix frags.
// Operands are pre-rounded to tf32 grid by producers (MMA truncation exact).
//   CAUSAL=1: skip blocks fully above diagonal
//   CAPK=1:   cap k-loop at m0+128 (PV over zero-padded causal probs)
//   ROUND=1:  round outputs to tf32 grid (outputs feed another MMA)
//   RES=1:    add residual (final output)
// ===========================================================================
#define BK 32
#define TILE_B (128 * BK * 4)    // 16 KB per tile buffer
#define NSTAGE 3
#define SM_A 0
#define SM_B (NSTAGE * TILE_B)
#define SM_TOT (2 * NSTAGE * TILE_B)   // 96 KB

template<int CAUSAL, int CAPK, int ROUND, int RES>
__global__ void __launch_bounds__(256)
gemm_nt_tc(const float* __restrict__ A,
           const float* __restrict__ B,
           float* __restrict__ C,
           const float* __restrict__ res,
           int M, int N, int K,
           int lda, int ldb, int ldc,
           float scale)
{
    extern __shared__ char smem[];
    int m0 = blockIdx.y * 128;
    int n0 = blockIdx.x * 128;
    if (CAUSAL && n0 > m0 + 127) return;

    uint32_t sbase = smem_u32(smem);
    int t    = threadIdx.x;
    int lane = t & 31;
    int warp = t >> 5;
    int gid  = lane >> 2;
    int tig  = lane & 3;
    int wm   = (warp >> 2) * 64;
    int wn   = (warp & 3) * 32;

    int kend  = CAPK ? min(K, m0 + 128) : K;
    int niter = kend / BK;

    auto load_tiles = [&](int buf, int k0) {
        #pragma unroll
        for (int i = 0; i < 4; i++) {
            int f = t + i * 256;
            int row = f >> 3, kg = f & 7;
            uint32_t off = SW128((uint32_t)(row * 128 + kg * 16));
            CP_ASYNC16(sbase + SM_A + buf * TILE_B + off,
                       A + (size_t)(m0 + row) * lda + k0 + kg * 4);
        }
        #pragma unroll
        for (int i = 0; i < 4; i++) {
            int f = t + i * 256;
            int row = f >> 3, kg = f & 7;
            uint32_t off = SW128((uint32_t)(row * 128 + kg * 16));
            CP_ASYNC16(sbase + SM_B + buf * TILE_B + off,
                       B + (size_t)(n0 + row) * ldb + k0 + kg * 4);
        }
    };

    float acc[4][4][4];
    #pragma unroll
    for (int mi = 0; mi < 4; mi++)
        #pragma unroll
        for (int ni = 0; ni < 4; ni++)
            #pragma unroll
            for (int r = 0; r < 4; r++) acc[mi][ni][r] = 0.0f;

    // per-thread ldmatrix address components
    int q   = lane >> 3;          // tile index within x4 (0..3)
    int r8  = lane & 7;           // row within tile
    int aq1 = (q & 1) * 8;        // A: +8 rows for tiles 1,3
    int aq2 = q >> 1;             // A: kg +1 for tiles 2,3
    int bq1 = (q >> 1) * 8;       // B: second n-tile for tiles 2,3
    int bq2 = q & 1;              // B: kg +1 for tiles 1,3

    // prologue: stage buffers 0 and 1
    load_tiles(0, 0);
    CP_COMMIT();
    if (niter > 1) load_tiles(1, BK);
    CP_COMMIT();

    int buf = 0;
    for (int it = 0; it < niter; it++) {
        CP_WAIT1();
        __syncthreads();

        uint32_t sa = sbase + SM_A + buf * TILE_B;
        uint32_t sb = sbase + SM_B + buf * TILE_B;

        // issue next-next tile load into the free buffer (read 3 iters ago)
        int nx = it + 2;
        int nbuf = buf + 2; if (nbuf >= NSTAGE) nbuf -= NSTAGE;
        if (nx < niter) load_tiles(nbuf, nx * BK);
        CP_COMMIT();

        #pragma unroll
        for (int ks = 0; ks < BK / 8; ks++) {
            uint32_t afr[4][4];
            #pragma unroll
            for (int mi = 0; mi < 4; mi++) {
                int row = wm + mi * 16 + aq1 + r8;
                int kg  = 2 * ks + aq2;
                uint32_t addr = sa + (uint32_t)(row * 128) + (uint32_t)(((kg) ^ (r8)) * 16);
                ldsm_x4(afr[mi][0], afr[mi][1], afr[mi][2], afr[mi][3], addr);
            }
            uint32_t bfr[4][2];
            #pragma unroll
            for (int p = 0; p < 2; p++) {
                int row = wn + p * 16 + bq1 + r8;
                int kg  = 2 * ks + bq2;
                uint32_t addr = sb + (uint32_t)(row * 128) + (uint32_t)(((kg) ^ (r8)) * 16);
                uint32_t r0, r1, r2, r3;
                ldsm_x4(r0, r1, r2, r3, addr);
                bfr[2 * p][0] = r0; bfr[2 * p][1] = r1;
                bfr[2 * p + 1][0] = r2; bfr[2 * p + 1][1] = r3;
            }
            #pragma unroll
            for (int mi = 0; mi < 4; mi++)
                #pragma unroll
                for (int ni = 0; ni < 4; ni++)
                    mma_tf32(acc[mi][ni], afr[mi], bfr[ni]);
        }

        buf++; if (buf >= NSTAGE) buf = 0;
    }

    // epilogue
    #pragma unroll
    for (int mi = 0; mi < 4; mi++) {
        #pragma unroll
        for (int ni = 0; ni < 4; ni++) {
            int row = m0 + wm + mi * 16 + gid;
            int col = n0 + wn + ni * 8 + tig * 2;
            float2 o0, o1;
            o0.x = acc[mi][ni][0] * scale;
            o0.y = acc[mi][ni][1] * scale;
            o1.x = acc[mi][ni][2] * scale;
            o1.y = acc[mi][ni][3] * scale;
            size_t i0 = (size_t)row * ldc + col;
            size_t i1 = (size_t)(row + 8) * ldc + col;
            if (RES) {
                float2 r0 = *(const float2*)(res + i0);
                float2 r1 = *(const float2*)(res + i1);
                o0.x += r0.x; o0.y += r0.y;
                o1.x += r1.x; o1.y += r1.y;
            }
            if (ROUND) {
                o0.x = rnd_tf32(o0.x); o0.y = rnd_tf32(o0.y);
                o1.x = rnd_tf32(o1.x); o1.y = rnd_tf32(o1.y);
            }
            *(float2*)(C + i0) = o0;
            *(float2*)(C + i1) = o1;
        }
    }
}

// ===========================================================================
// Causal row softmax over S (in place), float4 + __expf.
// Output probs rounded to tf32 grid; zero-pads to next 128-col boundary.
// ===========================================================================
__device__ __forceinline__ float block_reduce(float v, bool is_max)
{
    __shared__ float sm[8];
    __syncthreads();
    #pragma unroll
    for (int o = 16; o; o >>= 1) {
        float u = __shfl_xor_sync(0xffffffffu, v, o);
        v = is_max ? fmaxf(v, u) : (v + u);
    }
    int lane = threadIdx.x & 31, warp = threadIdx.x >> 5;
    if (lane == 0) sm[warp] = v;
    __syncthreads();
    float r = sm[0];
    #pragma unroll
    for (int i = 1; i < 8; i++)
        r = is_max ? fmaxf(r, sm[i]) : (r + sm[i]);
    return r;
}

__global__ void softmax_causal(float* __restrict__ S)
{
    int row = blockIdx.x;
    int t = threadIdx.x;               // 0..255
    int n = row + 1;
    float4* Srow = (float4*)(S + (size_t)row * T_DIM);

    float4 v[8];
    float mx = -INFINITY;
    #pragma unroll
    for (int it = 0; it < 8; it++) {
        int j0 = ((it << 8) + t) << 2;
        float4 x = (j0 < n) ? Srow[(it << 8) + t]
                            : make_float4(-INFINITY, -INFINITY, -INFINITY, -INFINITY);
        if (j0 + 1 >= n) x.y = -INFINITY;
        if (j0 + 2 >= n) x.z = -INFINITY;
        if (j0 + 3 >= n) x.w = -INFINITY;
        v[it] = x;
        mx = fmaxf(mx, fmaxf(fmaxf(x.x, x.y), fmaxf(x.z, x.w)));
    }
    mx = block_reduce(mx, true);

    float sum = 0.0f;
    #pragma unroll
    for (int it = 0; it < 8; it++) {
        float4 x = v[it];
        x.x = (x.x == -INFINITY) ? 0.0f : __expf(x.x - mx);
        x.y = (x.y == -INFINITY) ? 0.0f : __expf(x.y - mx);
        x.z = (x.z == -INFINITY) ? 0.0f : __expf(x.z - mx);
        x.w = (x.w == -INFINITY) ? 0.0f : __expf(x.w - mx);
        v[it] = x;
        sum += x.x + x.y + x.z + x.w;
    }
    sum = block_reduce(sum, false);
    float inv = 1.0f / sum;

    int zend = (n + 127) & ~127;
    #pragma unroll
    for (int it = 0; it < 8; it++) {
        int j0 = ((it << 8) + t) << 2;
        if (j0 < zend) {
            float4 x = v[it];
            float4 o;
            o.x = rnd_tf32(x.x * inv);
            o.y = rnd_tf32(x.y * inv);
            o.z = rnd_tf32(x.z * inv);
            o.w = rnd_tf32(x.w * inv);
            Srow[(it << 8) + t] = o;
        }
    }
}

// ===========================================================================
extern "C" void kernel_launch(void* const* d_in, const int* in_sizes, int n_in,
                              void* d_out, int out_size)
{
    const float* h    = (const float*)d_in[0];
    const float* ln_w = (const float*)d_in[1];
    const float* ln_b = (const float*)d_in[2];
    const float* w_q  = (const float*)d_in[3];
    const float* w_k  = (const float*)d_in[4];
    const float* w_v  = (const float*)d_in[5];
    const float* w_o  = (const float*)d_in[6];
    float* out = (float*)d_out;

    float *hn, *q, *k, *v, *vt, *av, *S, *wr;
    cudaGetSymbolAddress((void**)&hn, g_hnorm);
    cudaGetSymbolAddress((void**)&q,  g_q);
    cudaGetSymbolAddress((void**)&k,  g_k);
    cudaGetSymbolAddress((void**)&v,  g_v);
    cudaGetSymbolAddress((void**)&vt, g_vt);
    cudaGetSymbolAddress((void**)&av, g_av);
    cudaGetSymbolAddress((void**)&S,  g_S);
    cudaGetSymbolAddress((void**)&wr, g_wr);
    float* wq_r = wr;
    float* wk_r = wr + 1 * D_DIM * D_DIM;
    float* wv_r = wr + 2 * D_DIM * D_DIM;
    float* wo_r = wr + 3 * D_DIM * D_DIM;

    cudaFuncSetAttribute((const void*)gemm_nt_tc<0,0,1,0>,
                         cudaFuncAttributeMaxDynamicSharedMemorySize, SM_TOT);
    cudaFuncSetAttribute((const void*)gemm_nt_tc<1,0,0,0>,
                         cudaFuncAttributeMaxDynamicSharedMemorySize, SM_TOT);
    cudaFuncSetAttribute((const void*)gemm_nt_tc<0,1,1,0>,
                         cudaFuncAttributeMaxDynamicSharedMemorySize, SM_TOT);
    cudaFuncSetAttribute((const void*)gemm_nt_tc<0,0,0,1>,
                         cudaFuncAttributeMaxDynamicSharedMemorySize, SM_TOT);

    const float inv_sqrt_d = 0.044194173824159216f;  // 1/sqrt(512)
    const int W4 = (D_DIM * D_DIM) / 4 / 256;        // 256 blocks

    // 0) Round weights to tf32 grid (one-shot, 4 MB)
    round_tf32_kernel<<<W4, 256>>>(w_q, wq_r);
    round_tf32_kernel<<<W4, 256>>>(w_k, wk_r);
    round_tf32_kernel<<<W4, 256>>>(w_v, wv_r);
    round_tf32_kernel<<<W4, 256>>>(w_o, wo_r);

    // 1) LayerNorm (tf32-rounded output)
    ln_kernel<<<T_DIM, 128>>>(h, ln_w, ln_b, hn);

    // 2) Q, K, V projections (NT, rounded outputs)
    dim3 gProj(D_DIM / 128, T_DIM / 128);  // (4, 64)
    gemm_nt_tc<0,0,1,0><<<gProj, 256, SM_TOT>>>(hn, wq_r, q, nullptr,
        T_DIM, D_DIM, D_DIM, D_DIM, D_DIM, D_DIM, 1.0f);
    gemm_nt_tc<0,0,1,0><<<gProj, 256, SM_TOT>>>(hn, wk_r, k, nullptr,
        T_DIM, D_DIM, D_DIM, D_DIM, D_DIM, D_DIM, 1.0f);
    gemm_nt_tc<0,0,1,0><<<gProj, 256, SM_TOT>>>(hn, wv_r, v, nullptr,
        T_DIM, D_DIM, D_DIM, D_DIM, D_DIM, D_DIM, 1.0f);

    // 2b) Transpose V -> Vt[d][T] (already rounded)
    dim3 gT(D_DIM / 32, T_DIM / 32);   // (16, 256)
    transpose_kernel<<<gT, 256>>>(v, vt);

    // 3) Scores = Q @ K^T * 1/sqrt(d), lower-tri blocks only (NT, causal)
    dim3 gScore(T_DIM / 128, T_DIM / 128);  // (64, 64)
    gemm_nt_tc<1,0,0,0><<<gScore, 256, SM_TOT>>>(q, k, S, nullptr,
        T_DIM, T_DIM, D_DIM, D_DIM, D_DIM, T_DIM, inv_sqrt_d);

    // 4) Causal softmax (in place, rounded probs, zero-pads to 128-col)
    softmax_causal<<<T_DIM, 256>>>(S);

    // 5) AV = softmax(S) @ Vt^T (NT, k-capped, rounded output)
    dim3 gPV(D_DIM / 128, T_DIM / 128);  // (4, 64)
    gemm_nt_tc<0,1,1,0><<<gPV, 256, SM_TOT>>>(S, vt, av, nullptr,
        T_DIM, D_DIM, T_DIM, T_DIM, T_DIM, D_DIM, 1.0f);

    // 6) out = h + AV @ W_o^T (NT with residual)
    gemm_nt_tc<0,0,0,1><<<gProj, 256, SM_TOT>>>(av, wo_r, out, h,
        T_DIM, D_DIM, D_DIM, D_DIM, D_DIM, D_DIM, 1.0f);
}

// round 6
// speedup vs baseline: 4.2592x; 1.0561x over previous
#include <cuda_runtime.h>
#include <math.h>
#include <stdint.h>

#define T_DIM 8192
#define D_DIM 512

// Scratch (allocation-free rule: __device__ globals)
__device__ float g_hnorm[T_DIM * D_DIM];
__device__ float g_q[T_DIM * D_DIM];
__device__ float g_k[T_DIM * D_DIM];
__device__ float g_v[T_DIM * D_DIM];
__device__ float g_vt[T_DIM * D_DIM];          // V transposed: [d][T]
__device__ float g_av[T_DIM * D_DIM];
__device__ float g_avp[2][T_DIM * D_DIM];      // PV split-K partials
__device__ float g_wr[4][D_DIM * D_DIM];       // tf32-rounded weights
__device__ float g_S[(size_t)T_DIM * T_DIM];   // 256 MB score matrix

// ===========================================================================
// Helpers
// ===========================================================================
__device__ __forceinline__ uint32_t smem_u32(const void* p) {
    uint32_t a;
    asm("{ .reg .u64 t; cvta.to.shared.u64 t, %1; cvt.u32.u64 %0, t; }" : "=r"(a) : "l"(p));
    return a;
}
__device__ __forceinline__ float rnd_tf32(float f) {
    uint32_t r;
    asm("cvt.rna.tf32.f32 %0, %1;" : "=r"(r) : "f"(f));
    return __uint_as_float(r);
}
#define SW128(o) ((o) ^ ((((uint32_t)(o)) >> 3) & 0x70))

#define CP_ASYNC16(dst, src) \
    asm volatile("cp.async.cg.shared.global [%0], [%1], 16;" :: "r"(dst), "l"(src) : "memory")
#define CP_COMMIT() asm volatile("cp.async.commit_group;" ::: "memory")
#define CP_WAIT1()  asm volatile("cp.async.wait_group 1;" ::: "memory")

__device__ __forceinline__ void ldsm_x4(uint32_t& r0, uint32_t& r1, uint32_t& r2, uint32_t& r3,
                                        uint32_t addr) {
    asm volatile("ldmatrix.sync.aligned.m8n8.x4.shared.b16 {%0,%1,%2,%3}, [%4];"
                 : "=r"(r0), "=r"(r1), "=r"(r2), "=r"(r3) : "r"(addr));
}

__device__ __forceinline__ void mma_tf32(float* c, const uint32_t* a, const uint32_t* b) {
    asm volatile(
        "mma.sync.aligned.m16n8k8.row.col.f32.tf32.tf32.f32 "
        "{%0,%1,%2,%3}, {%4,%5,%6,%7}, {%8,%9}, {%0,%1,%2,%3};"
        : "+f"(c[0]), "+f"(c[1]), "+f"(c[2]), "+f"(c[3])
        : "r"(a[0]), "r"(a[1]), "r"(a[2]), "r"(a[3]),
          "r"(b[0]), "r"(b[1]));
}

// ===========================================================================
// Round a buffer to the tf32 grid (float4 per thread)
// ===========================================================================
__global__ void round_tf32_kernel(const float* __restrict__ in, float* __restrict__ out)
{
    int i = blockIdx.x * 256 + threadIdx.x;
    float4 v = ((const float4*)in)[i];
    float4 o;
    o.x = rnd_tf32(v.x); o.y = rnd_tf32(v.y); o.z = rnd_tf32(v.z); o.w = rnd_tf32(v.w);
    ((float4*)out)[i] = o;
}

// ===========================================================================
// Reduce PV split-K partials: av = rnd_tf32(p0 + p1)
// ===========================================================================
__global__ void reduce_av_kernel(const float* __restrict__ p, float* __restrict__ out)
{
    int i = blockIdx.x * 256 + threadIdx.x;
    float4 a = ((const float4*)p)[i];
    float4 b = ((const float4*)(p + (size_t)T_DIM * D_DIM))[i];
    float4 o;
    o.x = rnd_tf32(a.x + b.x);
    o.y = rnd_tf32(a.y + b.y);
    o.z = rnd_tf32(a.z + b.z);
    o.w = rnd_tf32(a.w + b.w);
    ((float4*)out)[i] = o;
}

// ===========================================================================
// LayerNorm: one block (128 threads) per row; output rounded to tf32 grid
// ===========================================================================
__global__ void ln_kernel(const float* __restrict__ h,
                          const float* __restrict__ w,
                          const float* __restrict__ b,
                          float* __restrict__ out)
{
    int row = blockIdx.x;
    int t = threadIdx.x;
    const float4* hr = (const float4*)(h + (size_t)row * D_DIM);
    float4 x = hr[t];
    float s  = x.x + x.y + x.z + x.w;
    float ss = x.x * x.x + x.y * x.y + x.z * x.z + x.w * x.w;

    #pragma unroll
    for (int o = 16; o; o >>= 1) {
        s  += __shfl_xor_sync(0xffffffffu, s,  o);
        ss += __shfl_xor_sync(0xffffffffu, ss, o);
    }
    __shared__ float red[2][4];
    int lane = t & 31, warp = t >> 5;
    if (lane == 0) { red[0][warp] = s; red[1][warp] = ss; }
    __syncthreads();
    float a = red[0][0] + red[0][1] + red[0][2] + red[0][3];
    float c = red[1][0] + red[1][1] + red[1][2] + red[1][3];
    float mean = a * (1.0f / D_DIM);
    float var  = c * (1.0f / D_DIM) - mean * mean;
    float rstd = rsqrtf(var + 1e-5f);

    float4 wv = ((const float4*)w)[t];
    float4 bv = ((const float4*)b)[t];
    float4 o;
    o.x = rnd_tf32((x.x - mean) * rstd * wv.x + bv.x);
    o.y = rnd_tf32((x.y - mean) * rstd * wv.y + bv.y);
    o.z = rnd_tf32((x.z - mean) * rstd * wv.z + bv.z);
    o.w = rnd_tf32((x.w - mean) * rstd * wv.w + bv.w);
    ((float4*)(out + (size_t)row * D_DIM))[t] = o;
}

// ===========================================================================
// 32x32 tiled transpose: out[d][T] = in[T][d]
// ===========================================================================
__global__ void transpose_kernel(const float* __restrict__ in, float* __restrict__ out)
{
    __shared__ float tile[32][33];
    int x0 = blockIdx.x * 32;   // d
    int y0 = blockIdx.y * 32;   // T
    int tx = threadIdx.x & 31, ty = threadIdx.x >> 5;   // 32 x 8
    #pragma unroll
    for (int i = 0; i < 32; i += 8)
        tile[ty + i][tx] = in[(size_t)(y0 + ty + i) * D_DIM + x0 + tx];
    __syncthreads();
    #pragma unroll
    for (int i = 0; i < 32; i += 8)
        out[(size_t)(x0 + ty + i) * T_DIM + y0 + tx] = tile[tx][ty + i];
}

// ===========================================================================
// TF32 mma.sync GEMM (NT): C[M,N] = scale*(A[M,K] @ B[N,K]^T) (+res)
// 128x128x32 block tile, 4 warps (2x2), warp tile 64x64.
// 3-stage cp.async ring (SW128-swizzled 128B rows), ldmatrix frags.
// Operands pre-rounded to tf32 grid by producers (MMA truncation exact).
//   CAUSAL=1: skip blocks fully above diagonal
//   CAPK=1:   cap k-loop at m0+128 (PV over zero-padded causal probs)
//   ROUND=1:  round outputs to tf32 grid (outputs feed another MMA)
//   RES=1:    add residual (final output)
//   KSPLIT>0: split k-range across blockIdx.z, write raw partial to
//             C + z*M*ldc (scale/round/res ignored)
// ===========================================================================
#define BK 32
#define TILE_B (128 * BK * 4)    // 16 KB per tile buffer
#define NSTAGE 3
#define SM_A 0
#define SM_B (NSTAGE * TILE_B)
#define SM_TOT (2 * NSTAGE * TILE_B)   // 96 KB

template<int CAUSAL, int CAPK, int ROUND, int RES, int KSPLIT>
__global__ void __launch_bounds__(128, 2)
gemm_nt_tc(const float* __restrict__ A,
           const float* __restrict__ B,
           float* __restrict__ C,
           const float* __restrict__ res,
           int M, int N, int K,
           int lda, int ldb, int ldc,
           float scale)
{
    extern __shared__ char smem[];
    int m0 = blockIdx.y * 128;
    int n0 = blockIdx.x * 128;
    if (CAUSAL && n0 > m0 + 127) return;

    uint32_t sbase = smem_u32(smem);
    int t    = threadIdx.x;          // 0..127
    int lane = t & 31;
    int warp = t >> 5;               // 0..3
    int gid  = lane >> 2;
    int tig  = lane & 3;
    int wm   = (warp >> 1) * 64;     // 0,64
    int wn   = (warp & 1) * 64;      // 0,64

    int kend  = CAPK ? min(K, m0 + 128) : K;
    int iters = kend / BK;
    int it0 = 0, it1 = iters;
    if (KSPLIT > 0) {
        int z = blockIdx.z;
        it0 = (iters * z) / KSPLIT;
        it1 = (iters * (z + 1)) / KSPLIT;
        C += (size_t)blockIdx.z * M * ldc;
    }
    int niter = it1 - it0;

    auto load_tiles = [&](int buf, int k0) {
        #pragma unroll
        for (int i = 0; i < 8; i++) {
            int f = t + i * 128;
            int row = f >> 3, kg = f & 7;
            uint32_t off = SW128((uint32_t)(row * 128 + kg * 16));
            CP_ASYNC16(sbase + SM_A + buf * TILE_B + off,
                       A + (size_t)(m0 + row) * lda + k0 + kg * 4);
        }
        #pragma unroll
        for (int i = 0; i < 8; i++) {
            int f = t + i * 128;
            int row = f >> 3, kg = f & 7;
            uint32_t off = SW128((uint32_t)(row * 128 + kg * 16));
            CP_ASYNC16(sbase + SM_B + buf * TILE_B + off,
                       B + (size_t)(n0 + row) * ldb + k0 + kg * 4);
        }
    };

    float acc[4][8][4];
    #pragma unroll
    for (int mi = 0; mi < 4; mi++)
        #pragma unroll
        for (int ni = 0; ni < 8; ni++)
            #pragma unroll
            for (int r = 0; r < 4; r++) acc[mi][ni][r] = 0.0f;

    // per-thread ldmatrix address components
    int q   = lane >> 3;          // tile index within x4 (0..3)
    int r8  = lane & 7;           // row within tile
    int aq1 = (q & 1) * 8;        // A: +8 rows for tiles 1,3
    int aq2 = q >> 1;             // A: kg +1 for tiles 2,3
    int bq1 = (q >> 1) * 8;       // B: second n-tile for tiles 2,3
    int bq2 = q & 1;              // B: kg +1 for tiles 1,3

    // prologue: stage first two tiles
    load_tiles(0, it0 * BK);
    CP_COMMIT();
    if (niter > 1) load_tiles(1, (it0 + 1) * BK);
    CP_COMMIT();

    int buf = 0;
    for (int it = 0; it < niter; it++) {
        CP_WAIT1();
        __syncthreads();

        uint32_t sa = sbase + SM_A + buf * TILE_B;
        uint32_t sb = sbase + SM_B + buf * TILE_B;

        // issue next-next tile load into the free buffer
        int nx = it + 2;
        int nbuf = buf + 2; if (nbuf >= NSTAGE) nbuf -= NSTAGE;
        if (nx < niter) load_tiles(nbuf, (it0 + nx) * BK);
        CP_COMMIT();

        #pragma unroll
        for (int ks = 0; ks < BK / 8; ks++) {
            uint32_t afr[4][4];
            #pragma unroll
            for (int mi = 0; mi < 4; mi++) {
                int row = wm + mi * 16 + aq1 + r8;
                int kg  = 2 * ks + aq2;
                uint32_t addr = sa + (uint32_t)(row * 128) + (uint32_t)((kg ^ r8) * 16);
                ldsm_x4(afr[mi][0], afr[mi][1], afr[mi][2], afr[mi][3], addr);
            }
            uint32_t bfr[8][2];
            #pragma unroll
            for (int p = 0; p < 4; p++) {
                int row = wn + p * 16 + bq1 + r8;
                int kg  = 2 * ks + bq2;
                uint32_t addr = sb + (uint32_t)(row * 128) + (uint32_t)((kg ^ r8) * 16);
                uint32_t r0, r1, r2, r3;
                ldsm_x4(r0, r1, r2, r3, addr);
                bfr[2 * p][0] = r0; bfr[2 * p][1] = r1;
                bfr[2 * p + 1][0] = r2; bfr[2 * p + 1][1] = r3;
            }
            #pragma unroll
            for (int mi = 0; mi < 4; mi++)
                #pragma unroll
                for (int ni = 0; ni < 8; ni++)
                    mma_tf32(acc[mi][ni], afr[mi], bfr[ni]);
        }

        buf++; if (buf >= NSTAGE) buf = 0;
    }

    // epilogue
    #pragma unroll
    for (int mi = 0; mi < 4; mi++) {
        #pragma unroll
        for (int ni = 0; ni < 8; ni++) {
            int row = m0 + wm + mi * 16 + gid;
            int col = n0 + wn + ni * 8 + tig * 2;
            float2 o0, o1;
            o0.x = acc[mi][ni][0]; o0.y = acc[mi][ni][1];
            o1.x = acc[mi][ni][2]; o1.y = acc[mi][ni][3];
            if (!KSPLIT) {
                o0.x *= scale; o0.y *= scale; o1.x *= scale; o1.y *= scale;
            }
            size_t i0 = (size_t)row * ldc + col;
            size_t i1 = (size_t)(row + 8) * ldc + col;
            if (RES) {
                float2 r0 = *(const float2*)(res + i0);
                float2 r1 = *(const float2*)(res + i1);
                o0.x += r0.x; o0.y += r0.y;
                o1.x += r1.x; o1.y += r1.y;
            }
            if (ROUND) {
                o0.x = rnd_tf32(o0.x); o0.y = rnd_tf32(o0.y);
                o1.x = rnd_tf32(o1.x); o1.y = rnd_tf32(o1.y);
            }
            *(float2*)(C + i0) = o0;
            *(float2*)(C + i1) = o1;
        }
    }
}

// ===========================================================================
// Causal row softmax over S (in place), float4 + __expf.
// Output probs rounded to tf32 grid; zero-pads to next 128-col boundary.
// ===========================================================================
__device__ __forceinline__ float block_reduce(float v, bool is_max)
{
    __shared__ float sm[8];
    __syncthreads();
    #pragma unroll
    for (int o = 16; o; o >>= 1) {
        float u = __shfl_xor_sync(0xffffffffu, v, o);
        v = is_max ? fmaxf(v, u) : (v + u);
    }
    int lane = threadIdx.x & 31, warp = threadIdx.x >> 5;
    if (lane == 0) sm[warp] = v;
    __syncthreads();
    float r = sm[0];
    #pragma unroll
    for (int i = 1; i < 8; i++)
        r = is_max ? fmaxf(r, sm[i]) : (r + sm[i]);
    return r;
}

__global__ void softmax_causal(float* __restrict__ S)
{
    int row = blockIdx.x;
    int t = threadIdx.x;               // 0..255
    int n = row + 1;
    float4* Srow = (float4*)(S + (size_t)row * T_DIM);

    float4 v[8];
    float mx = -INFINITY;
    #pragma unroll
    for (int it = 0; it < 8; it++) {
        int j0 = ((it << 8) + t) << 2;
        float4 x = (j0 < n) ? Srow[(it << 8) + t]
                            : make_float4(-INFINITY, -INFINITY, -INFINITY, -INFINITY);
        if (j0 + 1 >= n) x.y = -INFINITY;
        if (j0 + 2 >= n) x.z = -INFINITY;
        if (j0 + 3 >= n) x.w = -INFINITY;
        v[it] = x;
        mx = fmaxf(mx, fmaxf(fmaxf(x.x, x.y), fmaxf(x.z, x.w)));
    }
    mx = block_reduce(mx, true);

    float sum = 0.0f;
    #pragma unroll
    for (int it = 0; it < 8; it++) {
        float4 x = v[it];
        x.x = (x.x == -INFINITY) ? 0.0f : __expf(x.x - mx);
        x.y = (x.y == -INFINITY) ? 0.0f : __expf(x.y - mx);
        x.z = (x.z == -INFINITY) ? 0.0f : __expf(x.z - mx);
        x.w = (x.w == -INFINITY) ? 0.0f : __expf(x.w - mx);
        v[it] = x;
        sum += x.x + x.y + x.z + x.w;
    }
    sum = block_reduce(sum, false);
    float inv = 1.0f / sum;

    int zend = (n + 127) & ~127;
    #pragma unroll
    for (int it = 0; it < 8; it++) {
        int j0 = ((it << 8) + t) << 2;
        if (j0 < zend) {
            float4 x = v[it];
            float4 o;
            o.x = rnd_tf32(x.x * inv);
            o.y = rnd_tf32(x.y * inv);
            o.z = rnd_tf32(x.z * inv);
            o.w = rnd_tf32(x.w * inv);
            Srow[(it << 8) + t] = o;
        }
    }
}

// ===========================================================================
extern "C" void kernel_launch(void* const* d_in, const int* in_sizes, int n_in,
                              void* d_out, int out_size)
{
    const float* h    = (const float*)d_in[0];
    const float* ln_w = (const float*)d_in[1];
    const float* ln_b = (const float*)d_in[2];
    const float* w_q  = (const float*)d_in[3];
    const float* w_k  = (const float*)d_in[4];
    const float* w_v  = (const float*)d_in[5];
    const float* w_o  = (const float*)d_in[6];
    float* out = (float*)d_out;

    float *hn, *q, *k, *v, *vt, *av, *avp, *S, *wr;
    cudaGetSymbolAddress((void**)&hn,  g_hnorm);
    cudaGetSymbolAddress((void**)&q,   g_q);
    cudaGetSymbolAddress((void**)&k,   g_k);
    cudaGetSymbolAddress((void**)&v,   g_v);
    cudaGetSymbolAddress((void**)&vt,  g_vt);
    cudaGetSymbolAddress((void**)&av,  g_av);
    cudaGetSymbolAddress((void**)&avp, g_avp);
    cudaGetSymbolAddress((void**)&S,   g_S);
    cudaGetSymbolAddress((void**)&wr,  g_wr);
    float* wq_r = wr;
    float* wk_r = wr + 1 * D_DIM * D_DIM;
    float* wv_r = wr + 2 * D_DIM * D_DIM;
    float* wo_r = wr + 3 * D_DIM * D_DIM;

    cudaFuncSetAttribute((const void*)gemm_nt_tc<0,0,1,0,0>,
                         cudaFuncAttributeMaxDynamicSharedMemorySize, SM_TOT);
    cudaFuncSetAttribute((const void*)gemm_nt_tc<1,0,0,0,0>,
                         cudaFuncAttributeMaxDynamicSharedMemorySize, SM_TOT);
    cudaFuncSetAttribute((const void*)gemm_nt_tc<0,1,0,0,2>,
                         cudaFuncAttributeMaxDynamicSharedMemorySize, SM_TOT);
    cudaFuncSetAttribute((const void*)gemm_nt_tc<0,0,0,1,0>,
                         cudaFuncAttributeMaxDynamicSharedMemorySize, SM_TOT);

    const float inv_sqrt_d = 0.044194173824159216f;  // 1/sqrt(512)
    const int W4 = (D_DIM * D_DIM) / 4 / 256;        // 256 blocks

    // 0) Round weights to tf32 grid (one-shot, 4 MB)
    round_tf32_kernel<<<W4, 256>>>(w_q, wq_r);
    round_tf32_kernel<<<W4, 256>>>(w_k, wk_r);
    round_tf32_kernel<<<W4, 256>>>(w_v, wv_r);
    round_tf32_kernel<<<W4, 256>>>(w_o, wo_r);

    // 1) LayerNorm (tf32-rounded output)
    ln_kernel<<<T_DIM, 128>>>(h, ln_w, ln_b, hn);

    // 2) Q, K, V projections (NT, rounded outputs)
    dim3 gProj(D_DIM / 128, T_DIM / 128);  // (4, 64)
    gemm_nt_tc<0,0,1,0,0><<<gProj, 128, SM_TOT>>>(hn, wq_r, q, nullptr,
        T_DIM, D_DIM, D_DIM, D_DIM, D_DIM, D_DIM, 1.0f);
    gemm_nt_tc<0,0,1,0,0><<<gProj, 128, SM_TOT>>>(hn, wk_r, k, nullptr,
        T_DIM, D_DIM, D_DIM, D_DIM, D_DIM, D_DIM, 1.0f);
    gemm_nt_tc<0,0,1,0,0><<<gProj, 128, SM_TOT>>>(hn, wv_r, v, nullptr,
        T_DIM, D_DIM, D_DIM, D_DIM, D_DIM, D_DIM, 1.0f);

    // 2b) Transpose V -> Vt[d][T] (already rounded)
    dim3 gT(D_DIM / 32, T_DIM / 32);   // (16, 256)
    transpose_kernel<<<gT, 256>>>(v, vt);

    // 3) Scores = Q @ K^T * 1/sqrt(d), lower-tri blocks only (NT, causal)
    dim3 gScore(T_DIM / 128, T_DIM / 128);  // (64, 64)
    gemm_nt_tc<1,0,0,0,0><<<gScore, 128, SM_TOT>>>(q, k, S, nullptr,
        T_DIM, T_DIM, D_DIM, D_DIM, D_DIM, T_DIM, inv_sqrt_d);

    // 4) Causal softmax (in place, rounded probs, zero-pads to 128-col)
    softmax_causal<<<T_DIM, 256>>>(S);

    // 5) AV partials = softmax(S) @ Vt^T (NT, k-capped, split-K2)
    dim3 gPV(D_DIM / 128, T_DIM / 128, 2);  // (4, 64, 2)
    gemm_nt_tc<0,1,0,0,2><<<gPV, 128, SM_TOT>>>(S, vt, avp, nullptr,
        T_DIM, D_DIM, T_DIM, T_DIM, T_DIM, D_DIM, 1.0f);

    // 5b) av = rnd_tf32(p0 + p1)
    reduce_av_kernel<<<(T_DIM * D_DIM) / 4 / 256, 256>>>(avp, av);

    // 6) out = h + AV @ W_o^T (NT with residual)
    gemm_nt_tc<0,0,0,1,0><<<gProj, 128, SM_TOT>>>(av, wo_r, out, h,
        T_DIM, D_DIM, D_DIM, D_DIM, D_DIM, D_DIM, 1.0f);
}